// round 7
// baseline (speedup 1.0000x reference)
#include <cuda_runtime.h>
#include <cuda_bf16.h>
#include <math.h>

// ---------------------------------------------------------------------------
// MLA prefill, fp32. B=2 S=2048 HID=2048 NH=16 NOPE=128 ROPE=64 VD=128
// QKD=192 KVR=512 QR=1536
// ---------------------------------------------------------------------------

#define Bv    2
#define Sv    2048
#define HIDv  2048
#define NHv   16
#define NOPEv 128
#define ROPEv 64
#define VDv   128
#define QKDv  192
#define KVRv  512
#define QRv   1536
#define Tv    (Bv * Sv)                 // 4096 tokens
#define KVDIM (KVRv + ROPEv)            // 576
#define QDIM  (NHv * QKDv)              // 3072
#define KVXD  (NHv * (NOPEv + VDv))     // 4096
#define ODIM  (NHv * VDv)               // 2048
#define SCALEv 0.07216878364870322f     // 192^-0.5

// ---- scratch (device globals: allocation-free) ----------------------------
__device__ float g_qlat[(size_t)Tv * QRv];
__device__ float g_q   [(size_t)Tv * QDIM];
__device__ float g_kv  [(size_t)Tv * KVDIM];
__device__ float g_kvx [(size_t)Tv * KVXD];
__device__ float g_kp  [(size_t)Tv * QDIM];
__device__ float g_attn[(size_t)Tv * ODIM];

// ---------------------------------------------------------------------------
// SGEMM: C[M,N] = A[M,K] * B[N,K]^T   (row-major, K contiguous; "NT")
// 128x128 tile, BK=16, 256 threads, 8x8 micro-tile, double-buffered smem
// with register prefetch: 1 __syncthreads per k-step, LDG latency hidden.
// Requires K%16==0, M%128==0; N edge guarded.
// ---------------------------------------------------------------------------
__global__ __launch_bounds__(256, 2)
void sgemm_nt(const float* __restrict__ A, int lda,
              const float* __restrict__ Bm, int ldb,
              float* __restrict__ C, int ldc,
              int M, int N, int K)
{
    __shared__ float As[2][16][132];
    __shared__ float Bs[2][16][132];

    const int tid = threadIdx.x;
    const int tx  = tid & 15;
    const int ty  = tid >> 4;
    const int m0  = blockIdx.y * 128;
    const int n0  = blockIdx.x * 128;

    // per-thread load coords (2 chunks of 256)
    int lrow[2], lc4[2];
#pragma unroll
    for (int l = 0; l < 2; l++) {
        int idx = tid + l * 256;
        lrow[l] = idx >> 2;
        lc4[l]  = (idx & 3) << 2;
    }

    float4 pa[2], pb[2];

    auto LOADG = [&](int k0) {
#pragma unroll
        for (int l = 0; l < 2; l++) {
            pa[l] = *(const float4*)(A + (size_t)(m0 + lrow[l]) * lda + k0 + lc4[l]);
            int n = n0 + lrow[l];
            pb[l] = make_float4(0.f, 0.f, 0.f, 0.f);
            if (n < N)
                pb[l] = *(const float4*)(Bm + (size_t)n * ldb + k0 + lc4[l]);
        }
    };
    auto STORES = [&](int buf) {
#pragma unroll
        for (int l = 0; l < 2; l++) {
            As[buf][lc4[l] + 0][lrow[l]] = pa[l].x;
            As[buf][lc4[l] + 1][lrow[l]] = pa[l].y;
            As[buf][lc4[l] + 2][lrow[l]] = pa[l].z;
            As[buf][lc4[l] + 3][lrow[l]] = pa[l].w;
            Bs[buf][lc4[l] + 0][lrow[l]] = pb[l].x;
            Bs[buf][lc4[l] + 1][lrow[l]] = pb[l].y;
            Bs[buf][lc4[l] + 2][lrow[l]] = pb[l].z;
            Bs[buf][lc4[l] + 3][lrow[l]] = pb[l].w;
        }
    };

    float acc[8][8];
#pragma unroll
    for (int i = 0; i < 8; i++)
#pragma unroll
        for (int j = 0; j < 8; j++) acc[i][j] = 0.f;

    LOADG(0);
    STORES(0);
    __syncthreads();

    int cur = 0;
    for (int k0 = 0; k0 < K; k0 += 16) {
        const bool has_next = (k0 + 16 < K);
        if (has_next) LOADG(k0 + 16);       // LDGs issue; consumed after compute

#pragma unroll
        for (int kk = 0; kk < 16; kk++) {
            float a[8], b[8];
            *(float4*)&a[0] = *(const float4*)&As[cur][kk][ty * 8];
            *(float4*)&a[4] = *(const float4*)&As[cur][kk][ty * 8 + 4];
            *(float4*)&b[0] = *(const float4*)&Bs[cur][kk][tx * 8];
            *(float4*)&b[4] = *(const float4*)&Bs[cur][kk][tx * 8 + 4];
#pragma unroll
            for (int i = 0; i < 8; i++)
#pragma unroll
                for (int j = 0; j < 8; j++)
                    acc[i][j] = fmaf(a[i], b[j], acc[i][j]);
        }

        if (has_next) STORES(cur ^ 1);
        __syncthreads();
        cur ^= 1;
    }

#pragma unroll
    for (int i = 0; i < 8; i++) {
        int m = m0 + ty * 8 + i;
        int n = n0 + tx * 8;
        if (m < M && n < N) {
            float* cp = C + (size_t)m * ldc + n;
            *(float4*)cp       = make_float4(acc[i][0], acc[i][1], acc[i][2], acc[i][3]);
            *(float4*)(cp + 4) = make_float4(acc[i][4], acc[i][5], acc[i][6], acc[i][7]);
        }
    }
}

// ---------------------------------------------------------------------------
// RMSNorm over rows x cols (row stride), in-place.
// ---------------------------------------------------------------------------
__global__ void rmsnorm_k(float* __restrict__ x, const float* __restrict__ gamma,
                          int cols, int stride)
{
    const int row = blockIdx.x;
    const int tid = threadIdx.x;
    float* p = x + (size_t)row * stride;

    float ss = 0.f;
    for (int i = tid; i < cols; i += 256) { float v = p[i]; ss += v * v; }
#pragma unroll
    for (int o = 16; o > 0; o >>= 1) ss += __shfl_xor_sync(0xffffffffu, ss, o);

    __shared__ float red[8];
    if ((tid & 31) == 0) red[tid >> 5] = ss;
    __syncthreads();
    if (tid < 8) {
        float v = red[tid];
#pragma unroll
        for (int o = 4; o > 0; o >>= 1) v += __shfl_xor_sync(0xffu, v, o);
        if (tid == 0) red[0] = v;
    }
    __syncthreads();

    const float inv = rsqrtf(red[0] / (float)cols + 1e-6f);
    for (int i = tid; i < cols; i += 256) p[i] = p[i] * inv * gamma[i];
}

// ---------------------------------------------------------------------------
// RoPE on q rope slice (per token, head, i<32), in-place.
// ---------------------------------------------------------------------------
__global__ void rope_q_k(float* __restrict__ q, const float* __restrict__ cosp,
                         const float* __restrict__ sinp)
{
    int idx = blockIdx.x * blockDim.x + threadIdx.x;
    if (idx >= Tv * NHv * 32) return;
    int t = idx >> 9;
    int r = idx & 511;
    int h = r >> 5;
    int i = r & 31;
    float* p = q + (size_t)t * QDIM + h * QKDv + NOPEv;
    float c0 = cosp[t * ROPEv + i],      s0 = sinp[t * ROPEv + i];
    float c1 = cosp[t * ROPEv + 32 + i], s1 = sinp[t * ROPEv + 32 + i];
    float x0 = p[i], x1 = p[i + 32];
    p[i]      = x0 * c0 - x1 * s0;
    p[i + 32] = x1 * c1 + x0 * s1;
}

// RoPE on shared k_rope (kv cols 512..575), in-place.
__global__ void rope_k_k(float* __restrict__ kv, const float* __restrict__ cosp,
                         const float* __restrict__ sinp)
{
    int idx = blockIdx.x * blockDim.x + threadIdx.x;
    if (idx >= Tv * 32) return;
    int t = idx >> 5;
    int i = idx & 31;
    float* p = kv + (size_t)t * KVDIM + KVRv;
    float c0 = cosp[t * ROPEv + i],      s0 = sinp[t * ROPEv + i];
    float c1 = cosp[t * ROPEv + 32 + i], s1 = sinp[t * ROPEv + 32 + i];
    float x0 = p[i], x1 = p[i + 32];
    p[i]      = x0 * c0 - x1 * s0;
    p[i + 32] = x1 * c1 + x0 * s1;
}

// Pack K per head: kp[t][h*192+d] = (d<128) ? kvx[t][h*256+d] : kv[t][512+d-128]
__global__ void kpack_k(const float* __restrict__ kvx, const float* __restrict__ kv,
                        float* __restrict__ kp)
{
    int idx = blockIdx.x * blockDim.x + threadIdx.x;
    if (idx >= Tv * QDIM) return;
    int t = idx / QDIM;
    int r = idx % QDIM;
    int h = r / QKDv;
    int d = r % QKDv;
    float v = (d < NOPEv) ? kvx[(size_t)t * KVXD + h * 256 + d]
                          : kv[(size_t)t * KVDIM + KVRv + (d - NOPEv)];
    kp[idx] = v;
}

// ---------------------------------------------------------------------------
// Causal flash attention, fp32. grid (S/32, NH, B), 256 threads.
// BQ=32 queries, BK=64 keys per tile. Static smem ~45 KB.
//  - K chunk stored transposed -> vectorized LDS.128 in S phase
//  - parallel online softmax (8 threads per query row)
// ---------------------------------------------------------------------------
#define BQ 32
#define BK 64
__global__ __launch_bounds__(256)
void attn_kernel(const float* __restrict__ Qg, const float* __restrict__ Kg,
                 const float* __restrict__ KVXg, float* __restrict__ Og)
{
    __shared__ float Qs[BQ][196];      // pre-scaled Q (broadcast reads)
    __shared__ float Ks[16][68];       // transposed K chunk: Ks[kk][key]
    __shared__ float Ss[BQ][65];       // scores -> probs
    __shared__ float Vs[16][128];      // V chunk
    __shared__ float s_m[BQ], s_l[BQ], s_alpha[BQ];

    const int tid = threadIdx.x;
    const int tx  = tid & 15;
    const int ty  = tid >> 4;
    const int q0  = blockIdx.x * BQ;
    const int h   = blockIdx.y;
    const int tb  = blockIdx.z * Sv;

    // load + scale Q tile
    for (int idx = tid; idx < BQ * 48; idx += 256) {
        int row = idx / 48;
        int c4  = (idx % 48) * 4;
        float4 v = *(const float4*)(Qg + (size_t)(tb + q0 + row) * QDIM + h * QKDv + c4);
        v.x *= SCALEv; v.y *= SCALEv; v.z *= SCALEv; v.w *= SCALEv;
        *(float4*)&Qs[row][c4] = v;
    }
    if (tid < BQ) { s_m[tid] = -1e30f; s_l[tid] = 0.f; }

    float acc[2][8];
#pragma unroll
    for (int i = 0; i < 2; i++)
#pragma unroll
        for (int j = 0; j < 8; j++) acc[i][j] = 0.f;

    const int ktmax = (q0 + BQ - 1) / BK;
    for (int kt = 0; kt <= ktmax; kt++) {
        const int k0 = kt * BK;

        // ---- S = Q K^T, chunked 16-wide over d=192 ----
        float sacc[2][4];
#pragma unroll
        for (int i = 0; i < 2; i++)
#pragma unroll
            for (int j = 0; j < 4; j++) sacc[i][j] = 0.f;

        for (int c = 0; c < 12; c++) {
            {
                int row = tid >> 2;          // key 0..63
                int c4  = (tid & 3) << 2;    // 0,4,8,12
                float4 v = *(const float4*)(Kg + (size_t)(tb + k0 + row) * QDIM
                                            + h * QKDv + c * 16 + c4);
                Ks[c4 + 0][row] = v.x; Ks[c4 + 1][row] = v.y;
                Ks[c4 + 2][row] = v.z; Ks[c4 + 3][row] = v.w;
            }
            __syncthreads();
#pragma unroll
            for (int kk = 0; kk < 16; kk++) {
                float a0 = Qs[ty * 2 + 0][c * 16 + kk];
                float a1 = Qs[ty * 2 + 1][c * 16 + kk];
                float bb[4];
                *(float4*)&bb[0] = *(const float4*)&Ks[kk][tx * 4];
#pragma unroll
                for (int j = 0; j < 4; j++) {
                    sacc[0][j] = fmaf(a0, bb[j], sacc[0][j]);
                    sacc[1][j] = fmaf(a1, bb[j], sacc[1][j]);
                }
            }
            __syncthreads();
        }

        // ---- causal mask + stage scores ----
#pragma unroll
        for (int i = 0; i < 2; i++) {
            int qg = q0 + ty * 2 + i;
#pragma unroll
            for (int j = 0; j < 4; j++) {
                int kg = k0 + tx * 4 + j;
                Ss[ty * 2 + i][tx * 4 + j] = (kg <= qg) ? sacc[i][j] : -1e30f;
            }
        }
        __syncthreads();

        // ---- parallel online softmax: 8 threads per query row ----
        {
            int r  = tid >> 3;          // 0..31
            int j0 = (tid & 7) * 8;     // 0,8,..,56
            float mold = s_m[r];
            float lm = -1e30f;
#pragma unroll
            for (int j = 0; j < 8; j++) lm = fmaxf(lm, Ss[r][j0 + j]);
#pragma unroll
            for (int o = 4; o > 0; o >>= 1)
                lm = fmaxf(lm, __shfl_xor_sync(0xffffffffu, lm, o));
            float mnew = fmaxf(mold, lm);
            float sum = 0.f;
#pragma unroll
            for (int j = 0; j < 8; j++) {
                float pv = __expf(Ss[r][j0 + j] - mnew);
                Ss[r][j0 + j] = pv;
                sum += pv;
            }
#pragma unroll
            for (int o = 4; o > 0; o >>= 1)
                sum += __shfl_xor_sync(0xffffffffu, sum, o);
            if ((tid & 7) == 0) {
                float alpha = __expf(mold - mnew);
                s_l[r]     = s_l[r] * alpha + sum;
                s_m[r]     = mnew;
                s_alpha[r] = alpha;
            }
        }
        __syncthreads();

        float al0 = s_alpha[ty * 2 + 0];
        float al1 = s_alpha[ty * 2 + 1];
#pragma unroll
        for (int j = 0; j < 8; j++) { acc[0][j] *= al0; acc[1][j] *= al1; }

        // ---- O += P V (V streamed 16 rows at a time from kvx) ----
        for (int kc = 0; kc < 4; kc++) {
            for (int idx = tid; idx < 512; idx += 256) {
                int row = idx >> 5;
                int c4  = (idx & 31) << 2;
                float4 v = *(const float4*)(KVXg + (size_t)(tb + k0 + kc * 16 + row) * KVXD
                                            + h * 256 + NOPEv + c4);
                *(float4*)&Vs[row][c4] = v;
            }
            __syncthreads();
#pragma unroll
            for (int kk = 0; kk < 16; kk++) {
                float p0 = Ss[ty * 2 + 0][kc * 16 + kk];
                float p1 = Ss[ty * 2 + 1][kc * 16 + kk];
                float vv[8];
                *(float4*)&vv[0] = *(const float4*)&Vs[kk][tx * 8];
                *(float4*)&vv[4] = *(const float4*)&Vs[kk][tx * 8 + 4];
#pragma unroll
                for (int j = 0; j < 8; j++) {
                    acc[0][j] = fmaf(p0, vv[j], acc[0][j]);
                    acc[1][j] = fmaf(p1, vv[j], acc[1][j]);
                }
            }
            __syncthreads();
        }
    }

    // ---- normalize + store ----
#pragma unroll
    for (int i = 0; i < 2; i++) {
        int r = ty * 2 + i;
        float inv = 1.0f / s_l[r];
        float* op = Og + (size_t)(tb + q0 + r) * ODIM + h * VDv + tx * 8;
        *(float4*)op       = make_float4(acc[i][0] * inv, acc[i][1] * inv,
                                         acc[i][2] * inv, acc[i][3] * inv);
        *(float4*)(op + 4) = make_float4(acc[i][4] * inv, acc[i][5] * inv,
                                         acc[i][6] * inv, acc[i][7] * inv);
    }
}

// ---------------------------------------------------------------------------
extern "C" void kernel_launch(void* const* d_in, const int* in_sizes, int n_in,
                              void* d_out, int out_size)
{
    const float* hid      = (const float*)d_in[0];
    const float* cosp     = (const float*)d_in[1];
    const float* sinp     = (const float*)d_in[2];
    const float* Wq_down  = (const float*)d_in[3];
    const float* q_gamma  = (const float*)d_in[4];
    const float* Wq_up    = (const float*)d_in[5];
    const float* Wkv_down = (const float*)d_in[6];
    const float* kv_gamma = (const float*)d_in[7];
    const float* Wkv_up   = (const float*)d_in[8];
    const float* Wo       = (const float*)d_in[9];
    float* out = (float*)d_out;

    float *qlat, *q, *kv, *kvx, *kp, *attn;
    cudaGetSymbolAddress((void**)&qlat, g_qlat);
    cudaGetSymbolAddress((void**)&q,    g_q);
    cudaGetSymbolAddress((void**)&kv,   g_kv);
    cudaGetSymbolAddress((void**)&kvx,  g_kvx);
    cudaGetSymbolAddress((void**)&kp,   g_kp);
    cudaGetSymbolAddress((void**)&attn, g_attn);

    const dim3 blk(256);

    // 1) q latent: [T,1536] = hid @ Wq_down^T
    sgemm_nt<<<dim3(QRv / 128, Tv / 128), blk>>>(hid, HIDv, Wq_down, HIDv,
                                                 qlat, QRv, Tv, QRv, HIDv);
    // 2) rmsnorm(q_lat)
    rmsnorm_k<<<Tv, 256>>>(qlat, q_gamma, QRv, QRv);
    // 3) q: [T,3072] = q_lat @ Wq_up^T
    sgemm_nt<<<dim3(QDIM / 128, Tv / 128), blk>>>(qlat, QRv, Wq_up, QRv,
                                                  q, QDIM, Tv, QDIM, QRv);
    // 4) rope on q
    rope_q_k<<<(Tv * NHv * 32) / 256, 256>>>(q, cosp, sinp);
    // 5) kv: [T,576] = hid @ Wkv_down^T
    sgemm_nt<<<dim3((KVDIM + 127) / 128, Tv / 128), blk>>>(hid, HIDv, Wkv_down, HIDv,
                                                           kv, KVDIM, Tv, KVDIM, HIDv);
    // 6) rmsnorm(c_kv) on first 512 cols
    rmsnorm_k<<<Tv, 256>>>(kv, kv_gamma, KVRv, KVDIM);
    // 7) rope on shared k_rope (cols 512..575)
    rope_k_k<<<(Tv * 32) / 256, 256>>>(kv, cosp, sinp);
    // 8) kvx: [T,4096] = c_kv_norm @ Wkv_up^T
    sgemm_nt<<<dim3(KVXD / 128, Tv / 128), blk>>>(kv, KVDIM, Wkv_up, KVRv,
                                                  kvx, KVXD, Tv, KVXD, KVRv);
    // 9) pack per-head K = [k_nope | k_rope]
    kpack_k<<<(Tv * QDIM) / 256, 256>>>(kvx, kv, kp);
    // 10) causal attention
    attn_kernel<<<dim3(Sv / BQ, NHv, Bv), 256>>>(q, kp, kvx, attn);
    // 11) output projection
    sgemm_nt<<<dim3(HIDv / 128, Tv / 128), blk>>>(attn, ODIM, Wo, ODIM,
                                                  out, HIDv, Tv, HIDv, ODIM);
}

// round 8
// speedup vs baseline: 1.0069x; 1.0069x over previous
#include <cuda_runtime.h>
#include <cuda_bf16.h>
#include <math.h>

// ---------------------------------------------------------------------------
// MLA prefill, fp32. B=2 S=2048 HID=2048 NH=16 NOPE=128 ROPE=64 VD=128
// QKD=192 KVR=512 QR=1536
// ---------------------------------------------------------------------------

#define Bv    2
#define Sv    2048
#define HIDv  2048
#define NHv   16
#define NOPEv 128
#define ROPEv 64
#define VDv   128
#define QKDv  192
#define KVRv  512
#define QRv   1536
#define Tv    (Bv * Sv)                 // 4096 tokens
#define KVDIM (KVRv + ROPEv)            // 576
#define QDIM  (NHv * QKDv)              // 3072
#define KVXD  (NHv * (NOPEv + VDv))     // 4096
#define ODIM  (NHv * VDv)               // 2048
#define SCALEv 0.07216878364870322f     // 192^-0.5

// ---- scratch (device globals: allocation-free) ----------------------------
__device__ float g_qlat[(size_t)Tv * QRv];
__device__ float g_q   [(size_t)Tv * QDIM];
__device__ float g_kv  [(size_t)Tv * KVDIM];
__device__ float g_kvx [(size_t)Tv * KVXD];
__device__ float g_kp  [(size_t)Tv * QDIM];
__device__ float g_attn[(size_t)Tv * ODIM];

// ---------------------------------------------------------------------------
// SGEMM: C[M,N] = A[M,K] * B[N,K]^T   (row-major, K contiguous; "NT")
// 128x128 tile, BK=16, 256 threads, 8x8 micro-tile, double-buffered smem
// with register prefetch: 1 __syncthreads per k-step, LDG latency hidden.
// Requires K%16==0, M%128==0; N edge guarded.
// ---------------------------------------------------------------------------
__global__ __launch_bounds__(256, 2)
void sgemm_nt(const float* __restrict__ A, int lda,
              const float* __restrict__ Bm, int ldb,
              float* __restrict__ C, int ldc,
              int M, int N, int K)
{
    __shared__ float As[2][16][132];
    __shared__ float Bs[2][16][132];

    const int tid = threadIdx.x;
    const int tx  = tid & 15;
    const int ty  = tid >> 4;
    const int m0  = blockIdx.y * 128;
    const int n0  = blockIdx.x * 128;

    // per-thread load coords (2 chunks of 256)
    int lrow[2], lc4[2];
#pragma unroll
    for (int l = 0; l < 2; l++) {
        int idx = tid + l * 256;
        lrow[l] = idx >> 2;
        lc4[l]  = (idx & 3) << 2;
    }

    float4 pa[2], pb[2];

    auto LOADG = [&](int k0) {
#pragma unroll
        for (int l = 0; l < 2; l++) {
            pa[l] = *(const float4*)(A + (size_t)(m0 + lrow[l]) * lda + k0 + lc4[l]);
            int n = n0 + lrow[l];
            pb[l] = make_float4(0.f, 0.f, 0.f, 0.f);
            if (n < N)
                pb[l] = *(const float4*)(Bm + (size_t)n * ldb + k0 + lc4[l]);
        }
    };
    auto STORES = [&](int buf) {
#pragma unroll
        for (int l = 0; l < 2; l++) {
            As[buf][lc4[l] + 0][lrow[l]] = pa[l].x;
            As[buf][lc4[l] + 1][lrow[l]] = pa[l].y;
            As[buf][lc4[l] + 2][lrow[l]] = pa[l].z;
            As[buf][lc4[l] + 3][lrow[l]] = pa[l].w;
            Bs[buf][lc4[l] + 0][lrow[l]] = pb[l].x;
            Bs[buf][lc4[l] + 1][lrow[l]] = pb[l].y;
            Bs[buf][lc4[l] + 2][lrow[l]] = pb[l].z;
            Bs[buf][lc4[l] + 3][lrow[l]] = pb[l].w;
        }
    };

    float acc[8][8];
#pragma unroll
    for (int i = 0; i < 8; i++)
#pragma unroll
        for (int j = 0; j < 8; j++) acc[i][j] = 0.f;

    LOADG(0);
    STORES(0);
    __syncthreads();

    int cur = 0;
    for (int k0 = 0; k0 < K; k0 += 16) {
        const bool has_next = (k0 + 16 < K);
        if (has_next) LOADG(k0 + 16);       // LDGs issue; consumed after compute

#pragma unroll
        for (int kk = 0; kk < 16; kk++) {
            float a[8], b[8];
            *(float4*)&a[0] = *(const float4*)&As[cur][kk][ty * 8];
            *(float4*)&a[4] = *(const float4*)&As[cur][kk][ty * 8 + 4];
            *(float4*)&b[0] = *(const float4*)&Bs[cur][kk][tx * 8];
            *(float4*)&b[4] = *(const float4*)&Bs[cur][kk][tx * 8 + 4];
#pragma unroll
            for (int i = 0; i < 8; i++)
#pragma unroll
                for (int j = 0; j < 8; j++)
                    acc[i][j] = fmaf(a[i], b[j], acc[i][j]);
        }

        if (has_next) STORES(cur ^ 1);
        __syncthreads();
        cur ^= 1;
    }

#pragma unroll
    for (int i = 0; i < 8; i++) {
        int m = m0 + ty * 8 + i;
        int n = n0 + tx * 8;
        if (m < M && n < N) {
            float* cp = C + (size_t)m * ldc + n;
            *(float4*)cp       = make_float4(acc[i][0], acc[i][1], acc[i][2], acc[i][3]);
            *(float4*)(cp + 4) = make_float4(acc[i][4], acc[i][5], acc[i][6], acc[i][7]);
        }
    }
}

// ---------------------------------------------------------------------------
// RMSNorm over rows x cols (row stride), in-place.
// ---------------------------------------------------------------------------
__global__ void rmsnorm_k(float* __restrict__ x, const float* __restrict__ gamma,
                          int cols, int stride)
{
    const int row = blockIdx.x;
    const int tid = threadIdx.x;
    float* p = x + (size_t)row * stride;

    float ss = 0.f;
    for (int i = tid; i < cols; i += 256) { float v = p[i]; ss += v * v; }
#pragma unroll
    for (int o = 16; o > 0; o >>= 1) ss += __shfl_xor_sync(0xffffffffu, ss, o);

    __shared__ float red[8];
    if ((tid & 31) == 0) red[tid >> 5] = ss;
    __syncthreads();
    if (tid < 8) {
        float v = red[tid];
#pragma unroll
        for (int o = 4; o > 0; o >>= 1) v += __shfl_xor_sync(0xffu, v, o);
        if (tid == 0) red[0] = v;
    }
    __syncthreads();

    const float inv = rsqrtf(red[0] / (float)cols + 1e-6f);
    for (int i = tid; i < cols; i += 256) p[i] = p[i] * inv * gamma[i];
}

// ---------------------------------------------------------------------------
// RoPE on q rope slice (per token, head, i<32), in-place.
// ---------------------------------------------------------------------------
__global__ void rope_q_k(float* __restrict__ q, const float* __restrict__ cosp,
                         const float* __restrict__ sinp)
{
    int idx = blockIdx.x * blockDim.x + threadIdx.x;
    if (idx >= Tv * NHv * 32) return;
    int t = idx >> 9;
    int r = idx & 511;
    int h = r >> 5;
    int i = r & 31;
    float* p = q + (size_t)t * QDIM + h * QKDv + NOPEv;
    float c0 = cosp[t * ROPEv + i],      s0 = sinp[t * ROPEv + i];
    float c1 = cosp[t * ROPEv + 32 + i], s1 = sinp[t * ROPEv + 32 + i];
    float x0 = p[i], x1 = p[i + 32];
    p[i]      = x0 * c0 - x1 * s0;
    p[i + 32] = x1 * c1 + x0 * s1;
}

// RoPE on shared k_rope (kv cols 512..575), in-place.
__global__ void rope_k_k(float* __restrict__ kv, const float* __restrict__ cosp,
                         const float* __restrict__ sinp)
{
    int idx = blockIdx.x * blockDim.x + threadIdx.x;
    if (idx >= Tv * 32) return;
    int t = idx >> 5;
    int i = idx & 31;
    float* p = kv + (size_t)t * KVDIM + KVRv;
    float c0 = cosp[t * ROPEv + i],      s0 = sinp[t * ROPEv + i];
    float c1 = cosp[t * ROPEv + 32 + i], s1 = sinp[t * ROPEv + 32 + i];
    float x0 = p[i], x1 = p[i + 32];
    p[i]      = x0 * c0 - x1 * s0;
    p[i + 32] = x1 * c1 + x0 * s1;
}

// Pack K per head: kp[t][h*192+d] = (d<128) ? kvx[t][h*256+d] : kv[t][512+d-128]
__global__ void kpack_k(const float* __restrict__ kvx, const float* __restrict__ kv,
                        float* __restrict__ kp)
{
    int idx = blockIdx.x * blockDim.x + threadIdx.x;
    if (idx >= Tv * QDIM) return;
    int t = idx / QDIM;
    int r = idx % QDIM;
    int h = r / QKDv;
    int d = r % QKDv;
    float v = (d < NOPEv) ? kvx[(size_t)t * KVXD + h * 256 + d]
                          : kv[(size_t)t * KVDIM + KVRv + (d - NOPEv)];
    kp[idx] = v;
}

// ---------------------------------------------------------------------------
// Causal flash attention, fp32. grid (S/32, NH, B), 256 threads.
// BQ=32 queries, BK=64 keys per tile. Static smem ~45 KB.
//  - K chunk stored transposed -> vectorized LDS.128 in S phase
//  - parallel online softmax (8 threads per query row)
// ---------------------------------------------------------------------------
#define BQ 32
#define BK 64
__global__ __launch_bounds__(256)
void attn_kernel(const float* __restrict__ Qg, const float* __restrict__ Kg,
                 const float* __restrict__ KVXg, float* __restrict__ Og)
{
    __shared__ float Qs[BQ][196];      // pre-scaled Q (broadcast reads)
    __shared__ float Ks[16][68];       // transposed K chunk: Ks[kk][key]
    __shared__ float Ss[BQ][65];       // scores -> probs
    __shared__ float Vs[16][128];      // V chunk
    __shared__ float s_m[BQ], s_l[BQ], s_alpha[BQ];

    const int tid = threadIdx.x;
    const int tx  = tid & 15;
    const int ty  = tid >> 4;
    const int q0  = blockIdx.x * BQ;
    const int h   = blockIdx.y;
    const int tb  = blockIdx.z * Sv;

    // load + scale Q tile
    for (int idx = tid; idx < BQ * 48; idx += 256) {
        int row = idx / 48;
        int c4  = (idx % 48) * 4;
        float4 v = *(const float4*)(Qg + (size_t)(tb + q0 + row) * QDIM + h * QKDv + c4);
        v.x *= SCALEv; v.y *= SCALEv; v.z *= SCALEv; v.w *= SCALEv;
        *(float4*)&Qs[row][c4] = v;
    }
    if (tid < BQ) { s_m[tid] = -1e30f; s_l[tid] = 0.f; }

    float acc[2][8];
#pragma unroll
    for (int i = 0; i < 2; i++)
#pragma unroll
        for (int j = 0; j < 8; j++) acc[i][j] = 0.f;

    const int ktmax = (q0 + BQ - 1) / BK;
    for (int kt = 0; kt <= ktmax; kt++) {
        const int k0 = kt * BK;

        // ---- S = Q K^T, chunked 16-wide over d=192 ----
        float sacc[2][4];
#pragma unroll
        for (int i = 0; i < 2; i++)
#pragma unroll
            for (int j = 0; j < 4; j++) sacc[i][j] = 0.f;

        for (int c = 0; c < 12; c++) {
            {
                int row = tid >> 2;          // key 0..63
                int c4  = (tid & 3) << 2;    // 0,4,8,12
                float4 v = *(const float4*)(Kg + (size_t)(tb + k0 + row) * QDIM
                                            + h * QKDv + c * 16 + c4);
                Ks[c4 + 0][row] = v.x; Ks[c4 + 1][row] = v.y;
                Ks[c4 + 2][row] = v.z; Ks[c4 + 3][row] = v.w;
            }
            __syncthreads();
#pragma unroll
            for (int kk = 0; kk < 16; kk++) {
                float a0 = Qs[ty * 2 + 0][c * 16 + kk];
                float a1 = Qs[ty * 2 + 1][c * 16 + kk];
                float bb[4];
                *(float4*)&bb[0] = *(const float4*)&Ks[kk][tx * 4];
#pragma unroll
                for (int j = 0; j < 4; j++) {
                    sacc[0][j] = fmaf(a0, bb[j], sacc[0][j]);
                    sacc[1][j] = fmaf(a1, bb[j], sacc[1][j]);
                }
            }
            __syncthreads();
        }

        // ---- causal mask + stage scores ----
#pragma unroll
        for (int i = 0; i < 2; i++) {
            int qg = q0 + ty * 2 + i;
#pragma unroll
            for (int j = 0; j < 4; j++) {
                int kg = k0 + tx * 4 + j;
                Ss[ty * 2 + i][tx * 4 + j] = (kg <= qg) ? sacc[i][j] : -1e30f;
            }
        }
        __syncthreads();

        // ---- parallel online softmax: 8 threads per query row ----
        {
            int r  = tid >> 3;          // 0..31
            int j0 = (tid & 7) * 8;     // 0,8,..,56
            float mold = s_m[r];
            float lm = -1e30f;
#pragma unroll
            for (int j = 0; j < 8; j++) lm = fmaxf(lm, Ss[r][j0 + j]);
#pragma unroll
            for (int o = 4; o > 0; o >>= 1)
                lm = fmaxf(lm, __shfl_xor_sync(0xffffffffu, lm, o));
            float mnew = fmaxf(mold, lm);
            float sum = 0.f;
#pragma unroll
            for (int j = 0; j < 8; j++) {
                float pv = __expf(Ss[r][j0 + j] - mnew);
                Ss[r][j0 + j] = pv;
                sum += pv;
            }
#pragma unroll
            for (int o = 4; o > 0; o >>= 1)
                sum += __shfl_xor_sync(0xffffffffu, sum, o);
            if ((tid & 7) == 0) {
                float alpha = __expf(mold - mnew);
                s_l[r]     = s_l[r] * alpha + sum;
                s_m[r]     = mnew;
                s_alpha[r] = alpha;
            }
        }
        __syncthreads();

        float al0 = s_alpha[ty * 2 + 0];
        float al1 = s_alpha[ty * 2 + 1];
#pragma unroll
        for (int j = 0; j < 8; j++) { acc[0][j] *= al0; acc[1][j] *= al1; }

        // ---- O += P V (V streamed 16 rows at a time from kvx) ----
        for (int kc = 0; kc < 4; kc++) {
            for (int idx = tid; idx < 512; idx += 256) {
                int row = idx >> 5;
                int c4  = (idx & 31) << 2;
                float4 v = *(const float4*)(KVXg + (size_t)(tb + k0 + kc * 16 + row) * KVXD
                                            + h * 256 + NOPEv + c4);
                *(float4*)&Vs[row][c4] = v;
            }
            __syncthreads();
#pragma unroll
            for (int kk = 0; kk < 16; kk++) {
                float p0 = Ss[ty * 2 + 0][kc * 16 + kk];
                float p1 = Ss[ty * 2 + 1][kc * 16 + kk];
                float vv[8];
                *(float4*)&vv[0] = *(const float4*)&Vs[kk][tx * 8];
                *(float4*)&vv[4] = *(const float4*)&Vs[kk][tx * 8 + 4];
#pragma unroll
                for (int j = 0; j < 8; j++) {
                    acc[0][j] = fmaf(p0, vv[j], acc[0][j]);
                    acc[1][j] = fmaf(p1, vv[j], acc[1][j]);
                }
            }
            __syncthreads();
        }
    }

    // ---- normalize + store ----
#pragma unroll
    for (int i = 0; i < 2; i++) {
        int r = ty * 2 + i;
        float inv = 1.0f / s_l[r];
        float* op = Og + (size_t)(tb + q0 + r) * ODIM + h * VDv + tx * 8;
        *(float4*)op       = make_float4(acc[i][0] * inv, acc[i][1] * inv,
                                         acc[i][2] * inv, acc[i][3] * inv);
        *(float4*)(op + 4) = make_float4(acc[i][4] * inv, acc[i][5] * inv,
                                         acc[i][6] * inv, acc[i][7] * inv);
    }
}

// ---------------------------------------------------------------------------
extern "C" void kernel_launch(void* const* d_in, const int* in_sizes, int n_in,
                              void* d_out, int out_size)
{
    const float* hid      = (const float*)d_in[0];
    const float* cosp     = (const float*)d_in[1];
    const float* sinp     = (const float*)d_in[2];
    const float* Wq_down  = (const float*)d_in[3];
    const float* q_gamma  = (const float*)d_in[4];
    const float* Wq_up    = (const float*)d_in[5];
    const float* Wkv_down = (const float*)d_in[6];
    const float* kv_gamma = (const float*)d_in[7];
    const float* Wkv_up   = (const float*)d_in[8];
    const float* Wo       = (const float*)d_in[9];
    float* out = (float*)d_out;

    float *qlat, *q, *kv, *kvx, *kp, *attn;
    cudaGetSymbolAddress((void**)&qlat, g_qlat);
    cudaGetSymbolAddress((void**)&q,    g_q);
    cudaGetSymbolAddress((void**)&kv,   g_kv);
    cudaGetSymbolAddress((void**)&kvx,  g_kvx);
    cudaGetSymbolAddress((void**)&kp,   g_kp);
    cudaGetSymbolAddress((void**)&attn, g_attn);

    const dim3 blk(256);

    // 1) q latent: [T,1536] = hid @ Wq_down^T
    sgemm_nt<<<dim3(QRv / 128, Tv / 128), blk>>>(hid, HIDv, Wq_down, HIDv,
                                                 qlat, QRv, Tv, QRv, HIDv);
    // 2) rmsnorm(q_lat)
    rmsnorm_k<<<Tv, 256>>>(qlat, q_gamma, QRv, QRv);
    // 3) q: [T,3072] = q_lat @ Wq_up^T
    sgemm_nt<<<dim3(QDIM / 128, Tv / 128), blk>>>(qlat, QRv, Wq_up, QRv,
                                                  q, QDIM, Tv, QDIM, QRv);
    // 4) rope on q
    rope_q_k<<<(Tv * NHv * 32) / 256, 256>>>(q, cosp, sinp);
    // 5) kv: [T,576] = hid @ Wkv_down^T
    sgemm_nt<<<dim3((KVDIM + 127) / 128, Tv / 128), blk>>>(hid, HIDv, Wkv_down, HIDv,
                                                           kv, KVDIM, Tv, KVDIM, HIDv);
    // 6) rmsnorm(c_kv) on first 512 cols
    rmsnorm_k<<<Tv, 256>>>(kv, kv_gamma, KVRv, KVDIM);
    // 7) rope on shared k_rope (cols 512..575)
    rope_k_k<<<(Tv * 32) / 256, 256>>>(kv, cosp, sinp);
    // 8) kvx: [T,4096] = c_kv_norm @ Wkv_up^T
    sgemm_nt<<<dim3(KVXD / 128, Tv / 128), blk>>>(kv, KVDIM, Wkv_up, KVRv,
                                                  kvx, KVXD, Tv, KVXD, KVRv);
    // 9) pack per-head K = [k_nope | k_rope]
    kpack_k<<<(Tv * QDIM) / 256, 256>>>(kvx, kv, kp);
    // 10) causal attention
    attn_kernel<<<dim3(Sv / BQ, NHv, Bv), 256>>>(q, kp, kvx, attn);
    // 11) output projection
    sgemm_nt<<<dim3(HIDv / 128, Tv / 128), blk>>>(attn, ODIM, Wo, ODIM,
                                                  out, HIDv, Tv, HIDv, ODIM);
}

// round 11
// speedup vs baseline: 1.4263x; 1.4165x over previous
#include <stdint.h>
#include <cuda_runtime.h>
#include <cuda_bf16.h>
#include <math.h>

// ---------------------------------------------------------------------------
// MLA prefill. B=2 S=2048 HID=2048 NH=16 NOPE=128 ROPE=64 VD=128
// QKD=192 KVR=512 QR=1536
// GEMMs: split-bf16 (hi/lo compensated) on tensor cores via mma.sync.
// Attention: fp32 flash kernel (unchanged from R7 baseline).
// ---------------------------------------------------------------------------

#define Bv    2
#define Sv    2048
#define HIDv  2048
#define NHv   16
#define NOPEv 128
#define ROPEv 64
#define VDv   128
#define QKDv  192
#define KVRv  512
#define QRv   1536
#define Tv    (Bv * Sv)                 // 4096 tokens
#define KVDIM (KVRv + ROPEv)            // 576
#define QDIM  (NHv * QKDv)              // 3072
#define KVXD  (NHv * (NOPEv + VDv))     // 4096
#define ODIM  (NHv * VDv)               // 2048
#define SCALEv 0.07216878364870322f     // 192^-0.5

// ---- fp32 scratch ---------------------------------------------------------
__device__ float g_qlat[(size_t)Tv * QRv];
__device__ float g_q   [(size_t)Tv * QDIM];
__device__ float g_kv  [(size_t)Tv * KVDIM];
__device__ float g_kvx [(size_t)Tv * KVXD];
__device__ float g_kp  [(size_t)Tv * QDIM];
__device__ float g_attn[(size_t)Tv * ODIM];

// ---- bf16 split scratch (K tripled: act = [hi|lo|hi], wgt = [hi|hi|lo]) ---
__device__ __nv_bfloat16 g_hidc [(size_t)Tv   * 3 * HIDv];
__device__ __nv_bfloat16 g_qlatc[(size_t)Tv   * 3 * QRv];
__device__ __nv_bfloat16 g_kvc  [(size_t)Tv   * 3 * KVRv];
__device__ __nv_bfloat16 g_attnc[(size_t)Tv   * 3 * ODIM];
__device__ __nv_bfloat16 g_wqd  [(size_t)QRv  * 3 * HIDv];
__device__ __nv_bfloat16 g_wqu  [(size_t)QDIM * 3 * QRv];
__device__ __nv_bfloat16 g_wkd  [(size_t)KVDIM* 3 * HIDv];
__device__ __nv_bfloat16 g_wku  [(size_t)KVXD * 3 * KVRv];
__device__ __nv_bfloat16 g_wo   [(size_t)HIDv * 3 * ODIM];

__device__ __forceinline__ uint32_t smem_u32(const void* p) {
    return (uint32_t)__cvta_generic_to_shared(p);
}

// ---------------------------------------------------------------------------
// Split conversion: activation layout [hi | lo | hi]
// ---------------------------------------------------------------------------
__global__ void cvt_act(const float* __restrict__ x, int ld, int cols,
                        __nv_bfloat16* __restrict__ y, int rows)
{
    int c4n = cols >> 2;
    int idx = blockIdx.x * blockDim.x + threadIdx.x;
    if (idx >= rows * c4n) return;
    int r = idx / c4n;
    int c = (idx - r * c4n) << 2;
    float4 v = *(const float4*)(x + (size_t)r * ld + c);
    __nv_bfloat16 h0 = __float2bfloat16(v.x), h1 = __float2bfloat16(v.y);
    __nv_bfloat16 h2 = __float2bfloat16(v.z), h3 = __float2bfloat16(v.w);
    __nv_bfloat16 l0 = __float2bfloat16(v.x - __bfloat162float(h0));
    __nv_bfloat16 l1 = __float2bfloat16(v.y - __bfloat162float(h1));
    __nv_bfloat16 l2 = __float2bfloat16(v.z - __bfloat162float(h2));
    __nv_bfloat16 l3 = __float2bfloat16(v.w - __bfloat162float(h3));
    __nv_bfloat16* yr = y + (size_t)r * 3 * cols;
    *(__nv_bfloat162*)(yr + c)            = __halves2bfloat162(h0, h1);
    *(__nv_bfloat162*)(yr + c + 2)        = __halves2bfloat162(h2, h3);
    *(__nv_bfloat162*)(yr + cols + c)     = __halves2bfloat162(l0, l1);
    *(__nv_bfloat162*)(yr + cols + c + 2) = __halves2bfloat162(l2, l3);
    *(__nv_bfloat162*)(yr + 2*cols + c)       = __halves2bfloat162(h0, h1);
    *(__nv_bfloat162*)(yr + 2*cols + c + 2)   = __halves2bfloat162(h2, h3);
}

// weight layout [hi | hi | lo]
__global__ void cvt_wgt(const float* __restrict__ x, int ld, int cols,
                        __nv_bfloat16* __restrict__ y, int rows)
{
    int c4n = cols >> 2;
    int idx = blockIdx.x * blockDim.x + threadIdx.x;
    if (idx >= rows * c4n) return;
    int r = idx / c4n;
    int c = (idx - r * c4n) << 2;
    float4 v = *(const float4*)(x + (size_t)r * ld + c);
    __nv_bfloat16 h0 = __float2bfloat16(v.x), h1 = __float2bfloat16(v.y);
    __nv_bfloat16 h2 = __float2bfloat16(v.z), h3 = __float2bfloat16(v.w);
    __nv_bfloat16 l0 = __float2bfloat16(v.x - __bfloat162float(h0));
    __nv_bfloat16 l1 = __float2bfloat16(v.y - __bfloat162float(h1));
    __nv_bfloat16 l2 = __float2bfloat16(v.z - __bfloat162float(h2));
    __nv_bfloat16 l3 = __float2bfloat16(v.w - __bfloat162float(h3));
    __nv_bfloat16* yr = y + (size_t)r * 3 * cols;
    *(__nv_bfloat162*)(yr + c)            = __halves2bfloat162(h0, h1);
    *(__nv_bfloat162*)(yr + c + 2)        = __halves2bfloat162(h2, h3);
    *(__nv_bfloat162*)(yr + cols + c)     = __halves2bfloat162(h0, h1);
    *(__nv_bfloat162*)(yr + cols + c + 2) = __halves2bfloat162(h2, h3);
    *(__nv_bfloat162*)(yr + 2*cols + c)       = __halves2bfloat162(l0, l1);
    *(__nv_bfloat162*)(yr + 2*cols + c + 2)   = __halves2bfloat162(l2, l3);
}

// ---------------------------------------------------------------------------
// HGEMM (bf16 in, fp32 out): C[M,N] = A[M,K3] * B[N,K3]^T  (both K-contiguous)
// 128x128 tile, BK=32, 256 threads = 8 warps, warp tile 64x32,
// mma.sync.m16n8k16.bf16, ldmatrix from padded smem (stride 40 -> no conflicts),
// double-buffered with register prefetch. K3%32==0, M%128==0; N edge guarded.
// ---------------------------------------------------------------------------
#define LDSg 40
__global__ __launch_bounds__(256)
void hgemm_nt(const __nv_bfloat16* __restrict__ A, int lda,
              const __nv_bfloat16* __restrict__ B, int ldb,
              float* __restrict__ C, int ldc,
              int M, int N, int K3)
{
    __shared__ __nv_bfloat16 As[2][128 * LDSg];
    __shared__ __nv_bfloat16 Bs[2][128 * LDSg];

    const int tid  = threadIdx.x;
    const int lane = tid & 31;
    const int wid  = tid >> 5;
    const int wm   = (wid >> 2) << 6;   // 0, 64
    const int wn   = (wid & 3) << 5;    // 0, 32, 64, 96
    const int m0   = blockIdx.y * 128;
    const int n0   = blockIdx.x * 128;

    int lrow[2], lcol[2];
#pragma unroll
    for (int l = 0; l < 2; l++) {
        int idx = tid + (l << 8);
        lrow[l] = idx >> 2;
        lcol[l] = (idx & 3) << 3;
    }

    uint4 pa[2], pb[2];
    auto LOADG = [&](int k0) {
#pragma unroll
        for (int l = 0; l < 2; l++) {
            pa[l] = *(const uint4*)(A + (size_t)(m0 + lrow[l]) * lda + k0 + lcol[l]);
            int n = n0 + lrow[l];
            pb[l] = make_uint4(0u, 0u, 0u, 0u);
            if (n < N)
                pb[l] = *(const uint4*)(B + (size_t)n * ldb + k0 + lcol[l]);
        }
    };
    auto STORES = [&](int buf) {
#pragma unroll
        for (int l = 0; l < 2; l++) {
            *(uint4*)&As[buf][lrow[l] * LDSg + lcol[l]] = pa[l];
            *(uint4*)&Bs[buf][lrow[l] * LDSg + lcol[l]] = pb[l];
        }
    };

    float acc[16][4];
#pragma unroll
    for (int i = 0; i < 16; i++)
#pragma unroll
        for (int j = 0; j < 4; j++) acc[i][j] = 0.f;

    LOADG(0);
    STORES(0);
    __syncthreads();

    const int rl   = lane & 15;
    const int khi  = (lane >> 4) << 3;   // 0 or 8

    int cur = 0;
    for (int k0 = 0; k0 < K3; k0 += 32) {
        const bool nxt = (k0 + 32 < K3);
        if (nxt) LOADG(k0 + 32);

#pragma unroll
        for (int ks = 0; ks < 2; ks++) {
            const int kb = ks * 16 + khi;
            uint32_t a[4][4], b[2][4];
#pragma unroll
            for (int i = 0; i < 4; i++) {
                uint32_t ad = smem_u32(&As[cur][(wm + i * 16 + rl) * LDSg + kb]);
                asm volatile("ldmatrix.sync.aligned.m8n8.x4.shared.b16 {%0,%1,%2,%3}, [%4];"
                             : "=r"(a[i][0]), "=r"(a[i][1]), "=r"(a[i][2]), "=r"(a[i][3])
                             : "r"(ad));
            }
#pragma unroll
            for (int j = 0; j < 2; j++) {
                uint32_t ad = smem_u32(&Bs[cur][(wn + j * 16 + rl) * LDSg + kb]);
                asm volatile("ldmatrix.sync.aligned.m8n8.x4.shared.b16 {%0,%1,%2,%3}, [%4];"
                             : "=r"(b[j][0]), "=r"(b[j][1]), "=r"(b[j][2]), "=r"(b[j][3])
                             : "r"(ad));
            }
#pragma unroll
            for (int i = 0; i < 4; i++)
#pragma unroll
                for (int jj = 0; jj < 4; jj++) {
                    float* c = acc[i * 4 + jj];
                    asm volatile(
                        "mma.sync.aligned.m16n8k16.row.col.f32.bf16.bf16.f32 "
                        "{%0,%1,%2,%3}, {%4,%5,%6,%7}, {%8,%9}, {%0,%1,%2,%3};"
                        : "+f"(c[0]), "+f"(c[1]), "+f"(c[2]), "+f"(c[3])
                        : "r"(a[i][0]), "r"(a[i][1]), "r"(a[i][2]), "r"(a[i][3]),
                          "r"(b[jj >> 1][jj & 1]), "r"(b[jj >> 1][(jj & 1) + 2]));
                }
        }

        if (nxt) STORES(cur ^ 1);
        __syncthreads();
        cur ^= 1;
    }

    const int row  = lane >> 2;
    const int colp = (lane & 3) << 1;
#pragma unroll
    for (int i = 0; i < 4; i++)
#pragma unroll
        for (int jj = 0; jj < 4; jj++) {
            int mb = m0 + wm + i * 16 + row;
            int nb = n0 + wn + jj * 8 + colp;
            if (nb < N) {
                float* c = acc[i * 4 + jj];
                *(float2*)&C[(size_t)mb * ldc + nb]       = make_float2(c[0], c[1]);
                *(float2*)&C[(size_t)(mb + 8) * ldc + nb] = make_float2(c[2], c[3]);
            }
        }
}

// ---------------------------------------------------------------------------
// RMSNorm over rows x cols (row stride), in-place.
// ---------------------------------------------------------------------------
__global__ void rmsnorm_k(float* __restrict__ x, const float* __restrict__ gamma,
                          int cols, int stride)
{
    const int row = blockIdx.x;
    const int tid = threadIdx.x;
    float* p = x + (size_t)row * stride;

    float ss = 0.f;
    for (int i = tid; i < cols; i += 256) { float v = p[i]; ss += v * v; }
#pragma unroll
    for (int o = 16; o > 0; o >>= 1) ss += __shfl_xor_sync(0xffffffffu, ss, o);

    __shared__ float red[8];
    if ((tid & 31) == 0) red[tid >> 5] = ss;
    __syncthreads();
    if (tid < 8) {
        float v = red[tid];
#pragma unroll
        for (int o = 4; o > 0; o >>= 1) v += __shfl_xor_sync(0xffu, v, o);
        if (tid == 0) red[0] = v;
    }
    __syncthreads();

    const float inv = rsqrtf(red[0] / (float)cols + 1e-6f);
    for (int i = tid; i < cols; i += 256) p[i] = p[i] * inv * gamma[i];
}

// ---------------------------------------------------------------------------
// RoPE kernels + K pack
// ---------------------------------------------------------------------------
__global__ void rope_q_k(float* __restrict__ q, const float* __restrict__ cosp,
                         const float* __restrict__ sinp)
{
    int idx = blockIdx.x * blockDim.x + threadIdx.x;
    if (idx >= Tv * NHv * 32) return;
    int t = idx >> 9;
    int r = idx & 511;
    int h = r >> 5;
    int i = r & 31;
    float* p = q + (size_t)t * QDIM + h * QKDv + NOPEv;
    float c0 = cosp[t * ROPEv + i],      s0 = sinp[t * ROPEv + i];
    float c1 = cosp[t * ROPEv + 32 + i], s1 = sinp[t * ROPEv + 32 + i];
    float x0 = p[i], x1 = p[i + 32];
    p[i]      = x0 * c0 - x1 * s0;
    p[i + 32] = x1 * c1 + x0 * s1;
}

__global__ void rope_k_k(float* __restrict__ kv, const float* __restrict__ cosp,
                         const float* __restrict__ sinp)
{
    int idx = blockIdx.x * blockDim.x + threadIdx.x;
    if (idx >= Tv * 32) return;
    int t = idx >> 5;
    int i = idx & 31;
    float* p = kv + (size_t)t * KVDIM + KVRv;
    float c0 = cosp[t * ROPEv + i],      s0 = sinp[t * ROPEv + i];
    float c1 = cosp[t * ROPEv + 32 + i], s1 = sinp[t * ROPEv + 32 + i];
    float x0 = p[i], x1 = p[i + 32];
    p[i]      = x0 * c0 - x1 * s0;
    p[i + 32] = x1 * c1 + x0 * s1;
}

__global__ void kpack_k(const float* __restrict__ kvx, const float* __restrict__ kv,
                        float* __restrict__ kp)
{
    int idx = blockIdx.x * blockDim.x + threadIdx.x;
    if (idx >= Tv * QDIM) return;
    int t = idx / QDIM;
    int r = idx % QDIM;
    int h = r / QKDv;
    int d = r % QKDv;
    float v = (d < NOPEv) ? kvx[(size_t)t * KVXD + h * 256 + d]
                          : kv[(size_t)t * KVDIM + KVRv + (d - NOPEv)];
    kp[idx] = v;
}

// ---------------------------------------------------------------------------
// Causal flash attention, fp32 (unchanged from passing baseline).
// ---------------------------------------------------------------------------
#define BQ 32
#define BK 64
__global__ __launch_bounds__(256)
void attn_kernel(const float* __restrict__ Qg, const float* __restrict__ Kg,
                 const float* __restrict__ KVXg, float* __restrict__ Og)
{
    __shared__ float Qs[BQ][196];
    __shared__ float Ks[16][68];
    __shared__ float Ss[BQ][65];
    __shared__ float Vs[16][128];
    __shared__ float s_m[BQ], s_l[BQ], s_alpha[BQ];

    const int tid = threadIdx.x;
    const int tx  = tid & 15;
    const int ty  = tid >> 4;
    const int q0  = blockIdx.x * BQ;
    const int h   = blockIdx.y;
    const int tb  = blockIdx.z * Sv;

    for (int idx = tid; idx < BQ * 48; idx += 256) {
        int row = idx / 48;
        int c4  = (idx % 48) * 4;
        float4 v = *(const float4*)(Qg + (size_t)(tb + q0 + row) * QDIM + h * QKDv + c4);
        v.x *= SCALEv; v.y *= SCALEv; v.z *= SCALEv; v.w *= SCALEv;
        *(float4*)&Qs[row][c4] = v;
    }
    if (tid < BQ) { s_m[tid] = -1e30f; s_l[tid] = 0.f; }

    float acc[2][8];
#pragma unroll
    for (int i = 0; i < 2; i++)
#pragma unroll
        for (int j = 0; j < 8; j++) acc[i][j] = 0.f;

    const int ktmax = (q0 + BQ - 1) / BK;
    for (int kt = 0; kt <= ktmax; kt++) {
        const int k0 = kt * BK;

        float sacc[2][4];
#pragma unroll
        for (int i = 0; i < 2; i++)
#pragma unroll
            for (int j = 0; j < 4; j++) sacc[i][j] = 0.f;

        for (int c = 0; c < 12; c++) {
            {
                int row = tid >> 2;
                int c4  = (tid & 3) << 2;
                float4 v = *(const float4*)(Kg + (size_t)(tb + k0 + row) * QDIM
                                            + h * QKDv + c * 16 + c4);
                Ks[c4 + 0][row] = v.x; Ks[c4 + 1][row] = v.y;
                Ks[c4 + 2][row] = v.z; Ks[c4 + 3][row] = v.w;
            }
            __syncthreads();
#pragma unroll
            for (int kk = 0; kk < 16; kk++) {
                float a0 = Qs[ty * 2 + 0][c * 16 + kk];
                float a1 = Qs[ty * 2 + 1][c * 16 + kk];
                float bb[4];
                *(float4*)&bb[0] = *(const float4*)&Ks[kk][tx * 4];
#pragma unroll
                for (int j = 0; j < 4; j++) {
                    sacc[0][j] = fmaf(a0, bb[j], sacc[0][j]);
                    sacc[1][j] = fmaf(a1, bb[j], sacc[1][j]);
                }
            }
            __syncthreads();
        }

#pragma unroll
        for (int i = 0; i < 2; i++) {
            int qg = q0 + ty * 2 + i;
#pragma unroll
            for (int j = 0; j < 4; j++) {
                int kg = k0 + tx * 4 + j;
                Ss[ty * 2 + i][tx * 4 + j] = (kg <= qg) ? sacc[i][j] : -1e30f;
            }
        }
        __syncthreads();

        {
            int r  = tid >> 3;
            int j0 = (tid & 7) * 8;
            float mold = s_m[r];
            float lm = -1e30f;
#pragma unroll
            for (int j = 0; j < 8; j++) lm = fmaxf(lm, Ss[r][j0 + j]);
#pragma unroll
            for (int o = 4; o > 0; o >>= 1)
                lm = fmaxf(lm, __shfl_xor_sync(0xffffffffu, lm, o));
            float mnew = fmaxf(mold, lm);
            float sum = 0.f;
#pragma unroll
            for (int j = 0; j < 8; j++) {
                float pv = __expf(Ss[r][j0 + j] - mnew);
                Ss[r][j0 + j] = pv;
                sum += pv;
            }
#pragma unroll
            for (int o = 4; o > 0; o >>= 1)
                sum += __shfl_xor_sync(0xffffffffu, sum, o);
            if ((tid & 7) == 0) {
                float alpha = __expf(mold - mnew);
                s_l[r]     = s_l[r] * alpha + sum;
                s_m[r]     = mnew;
                s_alpha[r] = alpha;
            }
        }
        __syncthreads();

        float al0 = s_alpha[ty * 2 + 0];
        float al1 = s_alpha[ty * 2 + 1];
#pragma unroll
        for (int j = 0; j < 8; j++) { acc[0][j] *= al0; acc[1][j] *= al1; }

        for (int kc = 0; kc < 4; kc++) {
            for (int idx = tid; idx < 512; idx += 256) {
                int row = idx >> 5;
                int c4  = (idx & 31) << 2;
                float4 v = *(const float4*)(KVXg + (size_t)(tb + k0 + kc * 16 + row) * KVXD
                                            + h * 256 + NOPEv + c4);
                *(float4*)&Vs[row][c4] = v;
            }
            __syncthreads();
#pragma unroll
            for (int kk = 0; kk < 16; kk++) {
                float p0 = Ss[ty * 2 + 0][kc * 16 + kk];
                float p1 = Ss[ty * 2 + 1][kc * 16 + kk];
                float vv[8];
                *(float4*)&vv[0] = *(const float4*)&Vs[kk][tx * 8];
                *(float4*)&vv[4] = *(const float4*)&Vs[kk][tx * 8 + 4];
#pragma unroll
                for (int j = 0; j < 8; j++) {
                    acc[0][j] = fmaf(p0, vv[j], acc[0][j]);
                    acc[1][j] = fmaf(p1, vv[j], acc[1][j]);
                }
            }
            __syncthreads();
        }
    }

#pragma unroll
    for (int i = 0; i < 2; i++) {
        int r = ty * 2 + i;
        float inv = 1.0f / s_l[r];
        float* op = Og + (size_t)(tb + q0 + r) * ODIM + h * VDv + tx * 8;
        *(float4*)op       = make_float4(acc[i][0] * inv, acc[i][1] * inv,
                                         acc[i][2] * inv, acc[i][3] * inv);
        *(float4*)(op + 4) = make_float4(acc[i][4] * inv, acc[i][5] * inv,
                                         acc[i][6] * inv, acc[i][7] * inv);
    }
}

// ---------------------------------------------------------------------------
static inline int cvt_grid(int rows, int cols) {
    return (rows * (cols >> 2) + 255) / 256;
}

extern "C" void kernel_launch(void* const* d_in, const int* in_sizes, int n_in,
                              void* d_out, int out_size)
{
    const float* hid      = (const float*)d_in[0];
    const float* cosp     = (const float*)d_in[1];
    const float* sinp     = (const float*)d_in[2];
    const float* Wq_down  = (const float*)d_in[3];
    const float* q_gamma  = (const float*)d_in[4];
    const float* Wq_up    = (const float*)d_in[5];
    const float* Wkv_down = (const float*)d_in[6];
    const float* kv_gamma = (const float*)d_in[7];
    const float* Wkv_up   = (const float*)d_in[8];
    const float* Wo       = (const float*)d_in[9];
    float* out = (float*)d_out;

    float *qlat, *q, *kv, *kvx, *kp, *attn;
    __nv_bfloat16 *hidc, *qlatc, *kvc, *attnc, *wqd, *wqu, *wkd, *wku, *wo;
    cudaGetSymbolAddress((void**)&qlat,  g_qlat);
    cudaGetSymbolAddress((void**)&q,     g_q);
    cudaGetSymbolAddress((void**)&kv,    g_kv);
    cudaGetSymbolAddress((void**)&kvx,   g_kvx);
    cudaGetSymbolAddress((void**)&kp,    g_kp);
    cudaGetSymbolAddress((void**)&attn,  g_attn);
    cudaGetSymbolAddress((void**)&hidc,  g_hidc);
    cudaGetSymbolAddress((void**)&qlatc, g_qlatc);
    cudaGetSymbolAddress((void**)&kvc,   g_kvc);
    cudaGetSymbolAddress((void**)&attnc, g_attnc);
    cudaGetSymbolAddress((void**)&wqd,   g_wqd);
    cudaGetSymbolAddress((void**)&wqu,   g_wqu);
    cudaGetSymbolAddress((void**)&wkd,   g_wkd);
    cudaGetSymbolAddress((void**)&wku,   g_wku);
    cudaGetSymbolAddress((void**)&wo,    g_wo);

    // ---- weight + input conversions (split-bf16) ----
    cvt_act<<<cvt_grid(Tv,   HIDv), 256>>>(hid,      HIDv, HIDv, hidc, Tv);
    cvt_wgt<<<cvt_grid(QRv,  HIDv), 256>>>(Wq_down,  HIDv, HIDv, wqd,  QRv);
    cvt_wgt<<<cvt_grid(QDIM, QRv ), 256>>>(Wq_up,    QRv,  QRv,  wqu,  QDIM);
    cvt_wgt<<<cvt_grid(KVDIM,HIDv), 256>>>(Wkv_down, HIDv, HIDv, wkd,  KVDIM);
    cvt_wgt<<<cvt_grid(KVXD, KVRv), 256>>>(Wkv_up,   KVRv, KVRv, wku,  KVXD);
    cvt_wgt<<<cvt_grid(HIDv, ODIM), 256>>>(Wo,       ODIM, ODIM, wo,   HIDv);

    // 1) q latent: [T,1536] = hid @ Wq_down^T
    hgemm_nt<<<dim3(QRv / 128, Tv / 128), 256>>>(hidc, 3 * HIDv, wqd, 3 * HIDv,
                                                 qlat, QRv, Tv, QRv, 3 * HIDv);
    // 2) rmsnorm(q_lat)
    rmsnorm_k<<<Tv, 256>>>(qlat, q_gamma, QRv, QRv);
    // 3) convert + q: [T,3072] = q_lat @ Wq_up^T
    cvt_act<<<cvt_grid(Tv, QRv), 256>>>(qlat, QRv, QRv, qlatc, Tv);
    hgemm_nt<<<dim3(QDIM / 128, Tv / 128), 256>>>(qlatc, 3 * QRv, wqu, 3 * QRv,
                                                  q, QDIM, Tv, QDIM, 3 * QRv);
    // 4) rope on q
    rope_q_k<<<(Tv * NHv * 32) / 256, 256>>>(q, cosp, sinp);
    // 5) kv: [T,576] = hid @ Wkv_down^T
    hgemm_nt<<<dim3((KVDIM + 127) / 128, Tv / 128), 256>>>(hidc, 3 * HIDv, wkd, 3 * HIDv,
                                                           kv, KVDIM, Tv, KVDIM, 3 * HIDv);
    // 6) rmsnorm(c_kv), 7) rope on k_rope
    rmsnorm_k<<<Tv, 256>>>(kv, kv_gamma, KVRv, KVDIM);
    rope_k_k<<<(Tv * 32) / 256, 256>>>(kv, cosp, sinp);
    // 8) convert + kvx: [T,4096] = c_kv_norm @ Wkv_up^T
    cvt_act<<<cvt_grid(Tv, KVRv), 256>>>(kv, KVDIM, KVRv, kvc, Tv);
    hgemm_nt<<<dim3(KVXD / 128, Tv / 128), 256>>>(kvc, 3 * KVRv, wku, 3 * KVRv,
                                                  kvx, KVXD, Tv, KVXD, 3 * KVRv);
    // 9) pack per-head K
    kpack_k<<<(Tv * QDIM) / 256, 256>>>(kvx, kv, kp);
    // 10) causal attention (fp32)
    attn_kernel<<<dim3(Sv / BQ, NHv, Bv), 256>>>(q, kp, kvx, attn);
    // 11) convert + output projection
    cvt_act<<<cvt_grid(Tv, ODIM), 256>>>(attn, ODIM, ODIM, attnc, Tv);
    hgemm_nt<<<dim3(HIDv / 128, Tv / 128), 256>>>(attnc, 3 * ODIM, wo, 3 * ODIM,
                                                  out, HIDv, Tv, HIDv, 3 * ODIM);
}